// round 8
// baseline (speedup 1.0000x reference)
#include <cuda_runtime.h>
#include <math.h>

#define Nn 10000
#define Ee 320000
#define K1H 224          // per-head K for layer-1 GEMM (64 x + 64 e + 22 et + 8 nt + 64 res + 2 pad)
#define LDA1 (4 * K1H)   // 896
#define K2P 1408         // 1024 x + 256 e + 88 et + 32 nt + 8 pad

// ---------------- static scratch ----------------
__device__ int   d_src[Ee], d_dst[Ee], d_et[Ee], d_nt[Nn];
__device__ int   d_deg[Nn], d_off[Nn + 1], d_cur[Nn];
__device__ int   d_eid[Ee], d_srcS[Ee], d_etS[Ee];
__device__ float d_se1[Ee * 4], d_se2[Ee * 4];
__device__ float d_ssrc[Nn * 4], d_sdst[Nn * 4];
__device__ float d_h1[Nn * 256];
__device__ float d_v1[(size_t)Nn * LDA1], d_v2[(size_t)Nn * K2P];
__device__ float d_wsrc1[256], d_wdst1[256], d_wae1[256], d_etd1[22 * 4];
__device__ float d_wsrc2[1024], d_wdst2[1024], d_wae2[256], d_etd2[22 * 4];
__device__ float d_ntd1s[32], d_ntd1d[32], d_ntd2s[32], d_ntd2d[32];
__device__ float d_W1h[4 * K1H * 64], d_W2cat[K2P * 256];

typedef unsigned long long ull;

__device__ __forceinline__ float lrelu(float v) { return v > 0.f ? v : 0.2f * v; }
__device__ __forceinline__ int ldidx(const void* p, long long i, int is64) {
    return is64 ? (int)((const long long*)p)[i] : ((const int*)p)[i];
}
__device__ __forceinline__ ull dup2(float x) {
    ull r;
    asm("mov.b64 %0, {%1, %1};" : "=l"(r) : "r"(__float_as_uint(x)));
    return r;
}
__device__ __forceinline__ void fma2(ull& d, ull a, ull b) {
    asm("fma.rn.f32x2 %0, %1, %2, %0;" : "+l"(d) : "l"(a), "l"(b));
}
__device__ __forceinline__ float4 logit4(float4 ss, float4 sd, float4 se) {
    float4 l;
    l.x = lrelu(ss.x + sd.x + se.x); l.y = lrelu(ss.y + sd.y + se.y);
    l.z = lrelu(ss.z + sd.z + se.z); l.w = lrelu(ss.w + sd.w + se.w);
    return l;
}
__device__ __forceinline__ float4 warpMax4(float4 v) {
#pragma unroll
    for (int o = 16; o > 0; o >>= 1) {
        v.x = fmaxf(v.x, __shfl_xor_sync(0xffffffffu, v.x, o));
        v.y = fmaxf(v.y, __shfl_xor_sync(0xffffffffu, v.y, o));
        v.z = fmaxf(v.z, __shfl_xor_sync(0xffffffffu, v.z, o));
        v.w = fmaxf(v.w, __shfl_xor_sync(0xffffffffu, v.w, o));
    }
    return v;
}
__device__ __forceinline__ float4 warpSum4(float4 v) {
#pragma unroll
    for (int o = 16; o > 0; o >>= 1) {
        v.x += __shfl_xor_sync(0xffffffffu, v.x, o);
        v.y += __shfl_xor_sync(0xffffffffu, v.y, o);
        v.z += __shfl_xor_sync(0xffffffffu, v.z, o);
        v.w += __shfl_xor_sync(0xffffffffu, v.w, o);
    }
    return v;
}
__device__ __forceinline__ int block_is64(const unsigned int* w) {
    int t = threadIdx.x;
    int bad = 0;
    if (t < 128) bad = (w[2 * (t * 39) + 1] != 0u);
    return __syncthreads_or(bad) ? 0 : 1;
}

// ---------------- K1: fused preprocessing ----------------
#define PRE_CONV 1250
#define PRE_PW1  (PRE_CONV + 224)       // 4*224*64/256 = 224 blocks
#define PRE_PW2  (PRE_PW1 + 1408)       // 1408*256/256
#define PRE_TOT  (PRE_PW2 + 13)

__global__ void k_pre(const void* ei, const void* ntp, const void* etp,
                      const float* W1, const float* as1, const float* ad1,
                      const float* We1, const float* ag1, const float* etb1,
                      const float* W2, const float* as2, const float* ad2,
                      const float* We2, const float* ag2, const float* etb2,
                      const float* res1, const float* nte1, const float* nte2) {
    int b = blockIdx.x, t = threadIdx.x;
    if (b < PRE_CONV) {
        int is64 = block_is64((const unsigned int*)ntp);
        int e = b * 256 + t;
        if (e < Ee) {
            int s = ldidx(ei, e, is64);
            int d2 = ldidx(ei, (long long)Ee + e, is64);
            d_src[e] = s; d_dst[e] = d2; d_et[e] = ldidx(etp, e, is64);
            atomicAdd(&d_deg[d2], 1);
        }
        if (b < 40) { int i = b * 256 + t; if (i < Nn) d_nt[i] = ldidx(ntp, i, is64); }
    } else if (b < PRE_PW1) {
        int j = (b - PRE_CONV) * 256 + t;
        int c = j & 63, hk = j >> 6, h = hk / K1H, k = hk - h * K1H;
        float v = 0.f;
        if (k < 64) v = W1[k * 256 + h * 64 + c];
        else if (k < 128) v = We1[(k - 64) * 256 + h * 64 + c];
        else if (k < 150) v = etb1[(k - 128) * 256 + h * 64 + c];
        else if (k < 158) {
            int ty = k - 150; float s = 0.f;
            for (int cc = 0; cc < 64; cc++) s += nte1[ty * 64 + cc] * W1[cc * 256 + h * 64 + c];
            v = s;
        } else if (k < 222) v = res1[(k - 158) * 256 + h * 64 + c];
        d_W1h[j] = v;
    } else if (b < PRE_PW2) {
        int j = (b - PRE_PW1) * 256 + t;
        int col = j & 255, r = j >> 8;
        float v = 0.f;
        if (r < 1024) { int h = r >> 8, k = r & 255; v = W2[k * 1024 + h * 256 + col] * 0.25f; }
        else if (r < 1280) { int rr = r - 1024, h = rr >> 6, k = rr & 63; v = We2[k * 1024 + h * 256 + col] * 0.25f; }
        else if (r < 1368) { int rr = r - 1280, h = rr / 22, tt = rr % 22; v = etb2[tt * 1024 + h * 256 + col] * 0.25f; }
        else if (r < 1400) {
            int rr = r - 1368, h = rr >> 3, tt = rr & 7; float s = 0.f;
            for (int c = 0; c < 256; c++) s += nte2[tt * 256 + c] * W2[c * 1024 + h * 256 + col];
            v = s * 0.25f;
        }
        d_W2cat[j] = v;
    } else {
        int j = (b - PRE_PW2) * 256 + t;
        if (j < 256) {
            int h = j >> 6, k = j & 63; float s = 0.f;
            for (int c = 0; c < 64; c++) s += W1[k * 256 + h * 64 + c] * as1[h * 64 + c];
            d_wsrc1[j] = s;
        } else if (j < 512) {
            int jj = j - 256, h = jj >> 6, k = jj & 63; float s = 0.f;
            for (int c = 0; c < 64; c++) s += W1[k * 256 + h * 64 + c] * ad1[h * 64 + c];
            d_wdst1[jj] = s;
        } else if (j < 768) {
            int jj = j - 512, h = jj >> 6, k = jj & 63; float s = 0.f;
            for (int c = 0; c < 64; c++) s += We1[k * 256 + h * 64 + c] * ag1[h * 64 + c];
            d_wae1[jj] = s;
        } else if (j < 856) {
            int jj = j - 768, tt = jj >> 2, h = jj & 3; float s = 0.f;
            for (int c = 0; c < 64; c++) s += etb1[tt * 256 + h * 64 + c] * ag1[h * 64 + c];
            d_etd1[jj] = s;
        } else if (j < 1880) {
            int jj = j - 856, h = jj >> 8, k = jj & 255; float s = 0.f;
            for (int c = 0; c < 256; c++) s += W2[k * 1024 + h * 256 + c] * as2[h * 256 + c];
            d_wsrc2[jj] = s;
        } else if (j < 2904) {
            int jj = j - 1880, h = jj >> 8, k = jj & 255; float s = 0.f;
            for (int c = 0; c < 256; c++) s += W2[k * 1024 + h * 256 + c] * ad2[h * 256 + c];
            d_wdst2[jj] = s;
        } else if (j < 3160) {
            int jj = j - 2904, h = jj >> 6, k = jj & 63; float s = 0.f;
            for (int c = 0; c < 256; c++) s += We2[k * 1024 + h * 256 + c] * ag2[h * 256 + c];
            d_wae2[jj] = s;
        } else if (j < 3248) {
            int jj = j - 3160, tt = jj >> 2, h = jj & 3; float s = 0.f;
            for (int c = 0; c < 256; c++) s += etb2[tt * 1024 + h * 256 + c] * ag2[h * 256 + c];
            d_etd2[jj] = s;
        }
    }
}

// ---------------- K2: scan + zero deg + node-type score tables ----------------
__global__ void k_scan(const float* __restrict__ nte1, const float* __restrict__ nte2) {
    __shared__ int wsum[32];
    int t = threadIdx.x, base = t * 10, loc[10], sum = 0;
#pragma unroll
    for (int ii = 0; ii < 10; ii++) {
        int i = base + ii;
        int d = (i < Nn) ? d_deg[i] : 0;
        loc[ii] = d; sum += d;
    }
    int lane = t & 31, w = t >> 5;
    int v = sum;
#pragma unroll
    for (int o = 1; o < 32; o <<= 1) {
        int u = __shfl_up_sync(0xffffffffu, v, o);
        if (lane >= o) v += u;
    }
    if (lane == 31) wsum[w] = v;
    __syncthreads();
    if (w == 0) {
        int s = wsum[lane];
#pragma unroll
        for (int o = 1; o < 32; o <<= 1) {
            int u = __shfl_up_sync(0xffffffffu, s, o);
            if (lane >= o) s += u;
        }
        wsum[lane] = s;
    }
    __syncthreads();
    int run = v - sum + (w ? wsum[w - 1] : 0);
#pragma unroll
    for (int ii = 0; ii < 10; ii++) {
        int i = base + ii;
        if (i < Nn) { d_off[i] = run; d_cur[i] = run; d_deg[i] = 0; run += loc[ii]; }
        else if (i == Nn) d_off[Nn] = run;
    }
    // node-type score tables (weights written by k_pre; kernel boundary = sync)
    if (t < 128) {
        int which = t >> 5, i = t & 31, ty = i >> 2, h = i & 3;
        float s = 0.f;
        if (which == 0) { for (int k = 0; k < 64; k++) s += nte1[ty * 64 + k] * d_wsrc1[h * 64 + k]; d_ntd1s[i] = s; }
        else if (which == 1) { for (int k = 0; k < 64; k++) s += nte1[ty * 64 + k] * d_wdst1[h * 64 + k]; d_ntd1d[i] = s; }
        else if (which == 2) { for (int k = 0; k < 256; k++) s += nte2[ty * 256 + k] * d_wsrc2[h * 256 + k]; d_ntd2s[i] = s; }
        else { for (int k = 0; k < 256; k++) s += nte2[ty * 256 + k] * d_wdst2[h * 256 + k]; d_ntd2d[i] = s; }
    }
}

// ---------------- node score dot (no u materialization) ----------------
__device__ __forceinline__ void nscore_dot(int gw, int lane, const float* xin, int K,
                                           const float* ws, const float* wd,
                                           const float* ntds, const float* ntdd) {
    int nt = d_nt[gw];
    float ps[4] = {0, 0, 0, 0}, pd[4] = {0, 0, 0, 0};
    for (int k = lane; k < K; k += 32) {
        float v = xin[gw * K + k];
#pragma unroll
        for (int h = 0; h < 4; h++) { ps[h] += v * ws[h * K + k]; pd[h] += v * wd[h * K + k]; }
    }
#pragma unroll
    for (int h = 0; h < 4; h++)
        for (int o = 16; o > 0; o >>= 1) {
            ps[h] += __shfl_xor_sync(0xffffffffu, ps[h], o);
            pd[h] += __shfl_xor_sync(0xffffffffu, pd[h], o);
        }
    if (lane == 0)
#pragma unroll
        for (int h = 0; h < 4; h++) {
            d_ssrc[gw * 4 + h] = ps[h] + ntds[nt * 4 + h];
            d_sdst[gw * 4 + h] = pd[h] + ntdd[nt * 4 + h];
        }
}

// ---------------- K3: fused scatter + nscore1 + edgescore ----------------
#define MID_SCAT 1250
#define MID_NS   (MID_SCAT + 1250)
#define MID_TOT  (MID_NS + 40000)

__global__ void k_mid(const float* __restrict__ ea, const float* __restrict__ x) {
    int b = blockIdx.x, t = threadIdx.x;
    if (b < MID_SCAT) {
        int e = b * 256 + t;
        if (e < Ee) {
            int p = atomicAdd(&d_cur[d_dst[e]], 1);
            d_eid[p] = e; d_srcS[p] = d_src[e]; d_etS[p] = d_et[e];
        }
    } else if (b < MID_NS) {
        int gw = (b - MID_SCAT) * 8 + (t >> 5);
        if (gw < Nn) nscore_dot(gw, t & 31, x, 64, d_wsrc1, d_wdst1, d_ntd1s, d_ntd1d);
    } else {
        int e = (b - MID_NS) * 8 + (t >> 5);
        int lane = t & 31;
        float a0 = ea[(size_t)e * 64 + lane];
        float a1 = ea[(size_t)e * 64 + 32 + lane];
        float dd1[4], dd2[4];
#pragma unroll
        for (int h = 0; h < 4; h++) {
            dd1[h] = a0 * d_wae1[h * 64 + lane] + a1 * d_wae1[h * 64 + 32 + lane];
            dd2[h] = a0 * d_wae2[h * 64 + lane] + a1 * d_wae2[h * 64 + 32 + lane];
            for (int o = 16; o > 0; o >>= 1) {
                dd1[h] += __shfl_xor_sync(0xffffffffu, dd1[h], o);
                dd2[h] += __shfl_xor_sync(0xffffffffu, dd2[h], o);
            }
        }
        if (lane == 0) {
            int et = d_et[e];
#pragma unroll
            for (int h = 0; h < 4; h++) {
                d_se1[e * 4 + h] = dd1[h] + d_etd1[et * 4 + h];
                d_se2[e * 4 + h] = dd2[h] + d_etd2[et * 4 + h];
            }
        }
    }
}

// ---- warp softmax stats ----
__device__ __forceinline__ void warp_softmax(const float4* se4, int beg, int end,
                                             int lane, float4 sd, float4& m, float4& rdn) {
    const float4* ssrc4 = (const float4*)d_ssrc;
    float4 mx = make_float4(-1e30f, -1e30f, -1e30f, -1e30f);
    for (int i = beg + lane; i < end; i += 32) {
        float4 l = logit4(ssrc4[d_srcS[i]], sd, se4[d_eid[i]]);
        mx.x = fmaxf(mx.x, l.x); mx.y = fmaxf(mx.y, l.y);
        mx.z = fmaxf(mx.z, l.z); mx.w = fmaxf(mx.w, l.w);
    }
    m = warpMax4(mx);
    float4 sm = make_float4(0, 0, 0, 0);
    for (int i = beg + lane; i < end; i += 32) {
        float4 l = logit4(ssrc4[d_srcS[i]], sd, se4[d_eid[i]]);
        sm.x += __expf(l.x - m.x); sm.y += __expf(l.y - m.y);
        sm.z += __expf(l.z - m.z); sm.w += __expf(l.w - m.w);
    }
    float4 den = warpSum4(sm);
    rdn.x = 1.f / (den.x + 1e-16f); rdn.y = 1.f / (den.y + 1e-16f);
    rdn.z = 1.f / (den.z + 1e-16f); rdn.w = 1.f / (den.w + 1e-16f);
}

// ---------------- K4: warp-per-node layer-1 attention ----------------
__global__ void __launch_bounds__(256, 4)
k_attn1(const float* __restrict__ ea, const float* __restrict__ x) {
    int wid = threadIdx.x >> 5, lane = threadIdx.x & 31;
    int n = blockIdx.x * 8 + wid;
    __shared__ ull  aSh[8][32][4];
    __shared__ int2 iSh[8][32];
    __shared__ float acctSh[8][120];   // [0:88) etype, [88:120) ntype
    for (int i = lane; i < 120; i += 32) acctSh[wid][i] = 0.f;
    __syncwarp();
    int beg = d_off[n], end = d_off[n + 1], nE = end - beg;
    ull ax[4] = {0, 0, 0, 0}, av[4] = {0, 0, 0, 0};
    if (nE > 0) {
        const float4* ssrc4 = (const float4*)d_ssrc;
        const float4* se4 = (const float4*)d_se1;
        float4 sd = ((const float4*)d_sdst)[n];
        float4 m, rdn;
        warp_softmax(se4, beg, end, lane, sd, m, rdn);
        for (int c0 = beg; c0 < end; c0 += 32) {
            int nc = min(32, end - c0);
            if (lane < nc) {
                int i = c0 + lane;
                int s = d_srcS[i], e = d_eid[i], et = d_etS[i], ntj = d_nt[s];
                float4 l = logit4(ssrc4[s], sd, se4[e]);
                float a0 = __expf(l.x - m.x) * rdn.x, a1 = __expf(l.y - m.y) * rdn.y;
                float a2 = __expf(l.z - m.z) * rdn.z, a3 = __expf(l.w - m.w) * rdn.w;
                aSh[wid][lane][0] = dup2(a0); aSh[wid][lane][1] = dup2(a1);
                aSh[wid][lane][2] = dup2(a2); aSh[wid][lane][3] = dup2(a3);
                iSh[wid][lane] = make_int2(s, e);
                atomicAdd(&acctSh[wid][et], a0);
                atomicAdd(&acctSh[wid][22 + et], a1);
                atomicAdd(&acctSh[wid][44 + et], a2);
                atomicAdd(&acctSh[wid][66 + et], a3);
                atomicAdd(&acctSh[wid][88 + ntj], a0);
                atomicAdd(&acctSh[wid][96 + ntj], a1);
                atomicAdd(&acctSh[wid][104 + ntj], a2);
                atomicAdd(&acctSh[wid][112 + ntj], a3);
            }
            __syncwarp();
#pragma unroll 4
            for (int j = 0; j < nc; j++) {
                ull b0 = aSh[wid][j][0], b1 = aSh[wid][j][1];
                ull b2 = aSh[wid][j][2], b3 = aSh[wid][j][3];
                int2 se = iSh[wid][j];
                ull u = *(const ull*)&x[se.x * 64 + lane * 2];
                ull a = *(const ull*)&ea[(size_t)se.y * 64 + lane * 2];
                fma2(ax[0], u, b0); fma2(ax[1], u, b1);
                fma2(ax[2], u, b2); fma2(ax[3], u, b3);
                fma2(av[0], a, b0); fma2(av[1], a, b1);
                fma2(av[2], a, b2); fma2(av[3], a, b3);
            }
            __syncwarp();
        }
    }
    __syncwarp();
    float* v = &d_v1[(size_t)n * LDA1];
    int c = lane * 2;
#pragma unroll
    for (int h = 0; h < 4; h++) {
        *(ull*)&v[h * K1H + c] = ax[h];
        *(ull*)&v[h * K1H + 64 + c] = av[h];
        *(ull*)&v[h * K1H + 158 + c] = *(const ull*)&x[n * 64 + c];
    }
    for (int i = lane; i < 88; i += 32) {
        int hh = i / 22, t2 = i % 22;
        v[hh * K1H + 128 + t2] = acctSh[wid][i];
    }
    {   // ntype rows: head h, type t -> v[h*K1H + 150 + t]
        int hh = lane >> 3, tt = lane & 7;
        v[hh * K1H + 150 + tt] = acctSh[wid][88 + hh * 8 + tt];
    }
    if (lane < 8) v[(lane >> 1) * K1H + 222 + (lane & 1)] = 0.f;
}

// ---------------- K6: nscore layer 2 (dot only) ----------------
__global__ void k_ns2() {
    int gw = (blockIdx.x * blockDim.x + threadIdx.x) >> 5;
    if (gw < Nn) nscore_dot(gw, threadIdx.x & 31, d_h1, 256, d_wsrc2, d_wdst2, d_ntd2s, d_ntd2d);
}

// ---------------- K7: 2-warps-per-node layer-2 attention ----------------
__global__ void __launch_bounds__(256, 4)
k_attn2(const float* __restrict__ ea) {
    int wid = threadIdx.x >> 5, lane = threadIdx.x & 31;
    int pair = wid >> 1, half = wid & 1;
    int n = blockIdx.x * 4 + pair;
    __shared__ ull  aSh[8][32][4];
    __shared__ int2 iSh[8][32];
    __shared__ float acctSh[4][120];   // [0:88) etype (half0), [88:120) ntype (half1)
    if (half == 0) { for (int i = lane; i < 88; i += 32) acctSh[pair][i] = 0.f; }
    else { for (int i = 88 + lane; i < 120; i += 32) acctSh[pair][i] = 0.f; }
    __syncwarp();
    int beg = d_off[n], end = d_off[n + 1], nE = end - beg;
    int fbase = half * 128 + lane * 4;
    ull axu[4][2];
#pragma unroll
    for (int h = 0; h < 4; h++) { axu[h][0] = 0ull; axu[h][1] = 0ull; }
    ull av[4] = {0, 0, 0, 0};
    if (nE > 0) {
        const float4* ssrc4 = (const float4*)d_ssrc;
        const float4* se4 = (const float4*)d_se2;
        float4 sd = ((const float4*)d_sdst)[n];
        float4 m, rdn;
        warp_softmax(se4, beg, end, lane, sd, m, rdn);
        for (int c0 = beg; c0 < end; c0 += 32) {
            int nc = min(32, end - c0);
            if (lane < nc) {
                int i = c0 + lane;
                int s = d_srcS[i], e = d_eid[i], et = d_etS[i];
                float4 l = logit4(ssrc4[s], sd, se4[e]);
                float a0 = __expf(l.x - m.x) * rdn.x, a1 = __expf(l.y - m.y) * rdn.y;
                float a2 = __expf(l.z - m.z) * rdn.z, a3 = __expf(l.w - m.w) * rdn.w;
                aSh[wid][lane][0] = dup2(a0); aSh[wid][lane][1] = dup2(a1);
                aSh[wid][lane][2] = dup2(a2); aSh[wid][lane][3] = dup2(a3);
                iSh[wid][lane] = make_int2(s, e);
                if (half == 0) {
                    atomicAdd(&acctSh[pair][et], a0);
                    atomicAdd(&acctSh[pair][22 + et], a1);
                    atomicAdd(&acctSh[pair][44 + et], a2);
                    atomicAdd(&acctSh[pair][66 + et], a3);
                } else {
                    int ntj = d_nt[s];
                    atomicAdd(&acctSh[pair][88 + ntj], a0);
                    atomicAdd(&acctSh[pair][96 + ntj], a1);
                    atomicAdd(&acctSh[pair][104 + ntj], a2);
                    atomicAdd(&acctSh[pair][112 + ntj], a3);
                }
            }
            __syncwarp();
#pragma unroll 2
            for (int j = 0; j < nc; j++) {
                ull b0 = aSh[wid][j][0], b1 = aSh[wid][j][1];
                ull b2 = aSh[wid][j][2], b3 = aSh[wid][j][3];
                int2 se = iSh[wid][j];
                float4 u0 = *(const float4*)&d_h1[se.x * 256 + fbase];
                ull p0 = *(ull*)&u0.x, p1 = *(ull*)&u0.z;
                fma2(axu[0][0], p0, b0); fma2(axu[0][1], p1, b0);
                fma2(axu[1][0], p0, b1); fma2(axu[1][1], p1, b1);
                fma2(axu[2][0], p0, b2); fma2(axu[2][1], p1, b2);
                fma2(axu[3][0], p0, b3); fma2(axu[3][1], p1, b3);
                if (half == 0) {
                    ull a = *(const ull*)&ea[(size_t)se.y * 64 + lane * 2];
                    fma2(av[0], a, b0); fma2(av[1], a, b1);
                    fma2(av[2], a, b2); fma2(av[3], a, b3);
                }
            }
            __syncwarp();
        }
    }
    __syncwarp();
    float* v = &d_v2[(size_t)n * K2P];
#pragma unroll
    for (int h = 0; h < 4; h++) {
        *(ull*)&v[h * 256 + fbase] = axu[h][0];
        *(ull*)&v[h * 256 + fbase + 2] = axu[h][1];
    }
    if (half == 0) {
#pragma unroll
        for (int h = 0; h < 4; h++) *(ull*)&v[1024 + h * 64 + lane * 2] = av[h];
        for (int i = lane; i < 88; i += 32) v[1280 + i] = acctSh[pair][i];
    } else {
        v[1368 + lane] = acctSh[pair][88 + lane];
        if (lane < 8) v[1400 + lane] = 0.f;
    }
}

// ---------------- f32x2 packed SGEMM ----------------
template <int K, int MODE>
__global__ void k_gemmT(const float* __restrict__ A, const float* __restrict__ B,
                        const float* __restrict__ bias, const float* __restrict__ add,
                        float* __restrict__ C) {
    constexpr int LDA = (MODE == 1) ? LDA1 : K2P;
    __shared__ float As[8][132];
    __shared__ float Bs[8][64];
    int y = blockIdx.y;
    int bm = blockIdx.x * 128;
    int colbase = y * 64;
    const float* Ab = A + ((MODE == 1) ? y * K1H : 0);
    const float* Bb = (MODE == 1) ? (B + y * K1H * 64) : (B + colbase);
    const int ldb = (MODE == 1) ? 64 : 256;
    int tid = threadIdx.x;
    int tx = tid & 15, ty = tid >> 4;
    int lrow = tid >> 1, lk = (tid & 1) * 4;
    int brow = tid >> 4, bcol = (tid & 15) * 4;
    ull acc[4][4];
#pragma unroll
    for (int p = 0; p < 4; p++)
#pragma unroll
        for (int j = 0; j < 4; j++) acc[p][j] = 0ull;
    for (int k0 = 0; k0 < K; k0 += 8) {
        float4 avv = make_float4(0, 0, 0, 0);
        int row = bm + lrow;
        if (row < Nn) avv = *(const float4*)&Ab[(size_t)row * LDA + k0 + lk];
        As[lk + 0][lrow] = avv.x; As[lk + 1][lrow] = avv.y;
        As[lk + 2][lrow] = avv.z; As[lk + 3][lrow] = avv.w;
        if (tid < 128) {
            float4 bv = *(const float4*)&Bb[(size_t)(k0 + brow) * ldb + bcol];
            *(float4*)&Bs[brow][bcol] = bv;
        }
        __syncthreads();
#pragma unroll
        for (int kk = 0; kk < 8; kk++) {
            ulonglong2 a01 = *(const ulonglong2*)&As[kk][ty * 8];
            ulonglong2 a23 = *(const ulonglong2*)&As[kk][ty * 8 + 4];
            float4 bv = *(const float4*)&Bs[kk][tx * 4];
            ull ap[4] = {a01.x, a01.y, a23.x, a23.y};
            ull bd[4] = {dup2(bv.x), dup2(bv.y), dup2(bv.z), dup2(bv.w)};
#pragma unroll
            for (int p = 0; p < 4; p++)
#pragma unroll
                for (int j = 0; j < 4; j++) fma2(acc[p][j], ap[p], bd[j]);
        }
        __syncthreads();
    }
#pragma unroll
    for (int p = 0; p < 4; p++) {
        int r0 = bm + ty * 8 + 2 * p;
#pragma unroll
        for (int j = 0; j < 4; j++) {
            int col = colbase + tx * 4 + j;
            float lo = __uint_as_float((unsigned)(acc[p][j] & 0xffffffffull));
            float hi = __uint_as_float((unsigned)(acc[p][j] >> 32));
            float bsv = bias[col];
            if (r0 < Nn) {
                float v = lo + bsv;
                if (MODE == 1) v = fmaxf(v, 0.f);
                else v += add[r0 * 256 + col];
                C[r0 * 256 + col] = v;
            }
            if (r0 + 1 < Nn) {
                float v = hi + bsv;
                if (MODE == 1) v = fmaxf(v, 0.f);
                else v += add[(r0 + 1) * 256 + col];
                C[(r0 + 1) * 256 + col] = v;
            }
        }
    }
}

// ---------------- launch ----------------
extern "C" void kernel_launch(void* const* d_in, const int* in_sizes, int n_in,
                              void* d_out, int out_size) {
    const float* x    = (const float*)d_in[0];
    const void*  ei   = d_in[1];
    const void*  ntp  = d_in[2];
    const float* ea   = (const float*)d_in[3];
    const void*  etp  = d_in[4];
    const float* W1   = (const float*)d_in[5];
    const float* b1   = (const float*)d_in[6];
    const float* We1  = (const float*)d_in[7];
    const float* nte1 = (const float*)d_in[8];
    const float* ete1 = (const float*)d_in[9];
    const float* as1  = (const float*)d_in[10];
    const float* ad1  = (const float*)d_in[11];
    const float* ag1  = (const float*)d_in[12];
    const float* res1 = (const float*)d_in[13];
    const float* W2   = (const float*)d_in[14];
    const float* b2   = (const float*)d_in[15];
    const float* We2  = (const float*)d_in[16];
    const float* nte2 = (const float*)d_in[17];
    const float* ete2 = (const float*)d_in[18];
    const float* as2  = (const float*)d_in[19];
    const float* ad2  = (const float*)d_in[20];
    const float* ag2  = (const float*)d_in[21];
    float* out = (float*)d_out;

    k_pre<<<PRE_TOT, 256>>>(ei, ntp, etp, W1, as1, ad1, We1, ag1, ete1,
                            W2, as2, ad2, We2, ag2, ete2, res1, nte1, nte2);
    k_scan<<<1, 1024>>>(nte1, nte2);
    k_mid<<<MID_TOT, 256>>>(ea, x);
    k_attn1<<<Nn / 8, 256>>>(ea, x);

    float* h1;  cudaGetSymbolAddress((void**)&h1, d_h1);
    float* v1;  cudaGetSymbolAddress((void**)&v1, d_v1);
    float* w1h; cudaGetSymbolAddress((void**)&w1h, d_W1h);
    float* v2;  cudaGetSymbolAddress((void**)&v2, d_v2);
    float* w2c; cudaGetSymbolAddress((void**)&w2c, d_W2cat);
    dim3 g((Nn + 127) / 128, 4);
    k_gemmT<K1H, 1><<<g, 256>>>(v1, w1h, b1, nullptr, h1);
    k_ns2<<<(Nn * 32 + 255) / 256, 256>>>();
    k_attn2<<<Nn / 4, 256>>>(ea);
    k_gemmT<K2P, 2><<<g, 256>>>(v2, w2c, b2, h1, out);
}

// round 9
// speedup vs baseline: 1.0284x; 1.0284x over previous
#include <cuda_runtime.h>
#include <math.h>

#define Nn 10000
#define Ee 320000
#define K1H 216          // per-head K for layer-1 GEMM
#define LDA1 (4 * K1H)   // 864
#define K2P 1376

// ---------------- static scratch ----------------
__device__ int   d_src[Ee], d_dst[Ee], d_et[Ee], d_nt[Nn];
__device__ int   d_deg[Nn], d_off[Nn + 1], d_cur[Nn];
__device__ int   d_eid[Ee], d_srcS[Ee], d_etS[Ee];
__device__ float d_se1[Ee * 4], d_se2[Ee * 4];
__device__ float d_ssrc[Nn * 4], d_sdst[Nn * 4];
__device__ float d_u1[Nn * 64], d_u2[Nn * 256], d_h1[Nn * 256];
__device__ float d_v1[(size_t)Nn * LDA1], d_v2[(size_t)Nn * K2P];
__device__ float d_wsrc1[256], d_wdst1[256], d_wae1[256], d_etd1[22 * 4];
__device__ float d_wsrc2[1024], d_wdst2[1024], d_wae2[256], d_etd2[22 * 4];
__device__ float d_W1h[4 * K1H * 64], d_W2cat[K2P * 256];

typedef unsigned long long ull;

__device__ __forceinline__ float lrelu(float v) { return v > 0.f ? v : 0.2f * v; }
__device__ __forceinline__ int ldidx(const void* p, long long i, int is64) {
    return is64 ? (int)((const long long*)p)[i] : ((const int*)p)[i];
}
__device__ __forceinline__ ull dup2(float x) {
    ull r;
    asm("mov.b64 %0, {%1, %1};" : "=l"(r) : "r"(__float_as_uint(x)));
    return r;
}
__device__ __forceinline__ void fma2(ull& d, ull a, ull b) {
    asm("fma.rn.f32x2 %0, %1, %2, %0;" : "+l"(d) : "l"(a), "l"(b));
}
__device__ __forceinline__ float4 logit4(float4 ss, float4 sd, float4 se) {
    float4 l;
    l.x = lrelu(ss.x + sd.x + se.x); l.y = lrelu(ss.y + sd.y + se.y);
    l.z = lrelu(ss.z + sd.z + se.z); l.w = lrelu(ss.w + sd.w + se.w);
    return l;
}
__device__ __forceinline__ float4 warpMax4(float4 v) {
#pragma unroll
    for (int o = 16; o > 0; o >>= 1) {
        v.x = fmaxf(v.x, __shfl_xor_sync(0xffffffffu, v.x, o));
        v.y = fmaxf(v.y, __shfl_xor_sync(0xffffffffu, v.y, o));
        v.z = fmaxf(v.z, __shfl_xor_sync(0xffffffffu, v.z, o));
        v.w = fmaxf(v.w, __shfl_xor_sync(0xffffffffu, v.w, o));
    }
    return v;
}
__device__ __forceinline__ float4 warpSum4(float4 v) {
#pragma unroll
    for (int o = 16; o > 0; o >>= 1) {
        v.x += __shfl_xor_sync(0xffffffffu, v.x, o);
        v.y += __shfl_xor_sync(0xffffffffu, v.y, o);
        v.z += __shfl_xor_sync(0xffffffffu, v.z, o);
        v.w += __shfl_xor_sync(0xffffffffu, v.w, o);
    }
    return v;
}
__device__ __forceinline__ int block_is64(const unsigned int* w) {
    int t = threadIdx.x;
    int bad = 0;
    if (t < 128) bad = (w[2 * (t * 39) + 1] != 0u);
    return __syncthreads_or(bad) ? 0 : 1;
}

// ---------------- K1: fused preprocessing ----------------
#define PRE_CONV 1250
#define PRE_PW1  (PRE_CONV + 216)
#define PRE_PW2  (PRE_PW1 + 1376)
#define PRE_TOT  (PRE_PW2 + 13)

__global__ void k_pre(const void* ei, const void* ntp, const void* etp,
                      const float* W1, const float* as1, const float* ad1,
                      const float* We1, const float* ag1, const float* etb1,
                      const float* W2, const float* as2, const float* ad2,
                      const float* We2, const float* ag2, const float* etb2,
                      const float* res1) {
    int b = blockIdx.x, t = threadIdx.x;
    if (b < PRE_CONV) {
        int is64 = block_is64((const unsigned int*)ntp);
        int e = b * 256 + t;
        if (e < Ee) {
            int s = ldidx(ei, e, is64);
            int d2 = ldidx(ei, (long long)Ee + e, is64);
            d_src[e] = s; d_dst[e] = d2; d_et[e] = ldidx(etp, e, is64);
            atomicAdd(&d_deg[d2], 1);
        }
        if (b < 40) { int i = b * 256 + t; if (i < Nn) d_nt[i] = ldidx(ntp, i, is64); }
    } else if (b < PRE_PW1) {
        int j = (b - PRE_CONV) * 256 + t;
        int c = j & 63, hk = j >> 6, h = hk / K1H, k = hk - h * K1H;
        float v = 0.f;
        if (k < 64) v = W1[k * 256 + h * 64 + c];
        else if (k < 128) v = We1[(k - 64) * 256 + h * 64 + c];
        else if (k < 150) v = etb1[(k - 128) * 256 + h * 64 + c];
        else if (k < 214) v = res1[(k - 150) * 256 + h * 64 + c];
        d_W1h[j] = v;
    } else if (b < PRE_PW2) {
        int j = (b - PRE_PW1) * 256 + t;
        int col = j & 255, r = j >> 8;
        float v = 0.f;
        if (r < 1024) { int h = r >> 8, k = r & 255; v = W2[k * 1024 + h * 256 + col] * 0.25f; }
        else if (r < 1280) { int rr = r - 1024, h = rr >> 6, k = rr & 63; v = We2[k * 1024 + h * 256 + col] * 0.25f; }
        else if (r < 1368) { int rr = r - 1280, h = rr / 22, tt = rr % 22; v = etb2[tt * 1024 + h * 256 + col] * 0.25f; }
        d_W2cat[j] = v;
    } else {
        int j = (b - PRE_PW2) * 256 + t;
        if (j < 256) {
            int h = j >> 6, k = j & 63; float s = 0.f;
            for (int c = 0; c < 64; c++) s += W1[k * 256 + h * 64 + c] * as1[h * 64 + c];
            d_wsrc1[j] = s;
        } else if (j < 512) {
            int jj = j - 256, h = jj >> 6, k = jj & 63; float s = 0.f;
            for (int c = 0; c < 64; c++) s += W1[k * 256 + h * 64 + c] * ad1[h * 64 + c];
            d_wdst1[jj] = s;
        } else if (j < 768) {
            int jj = j - 512, h = jj >> 6, k = jj & 63; float s = 0.f;
            for (int c = 0; c < 64; c++) s += We1[k * 256 + h * 64 + c] * ag1[h * 64 + c];
            d_wae1[jj] = s;
        } else if (j < 856) {
            int jj = j - 768, tt = jj >> 2, h = jj & 3; float s = 0.f;
            for (int c = 0; c < 64; c++) s += etb1[tt * 256 + h * 64 + c] * ag1[h * 64 + c];
            d_etd1[jj] = s;
        } else if (j < 1880) {
            int jj = j - 856, h = jj >> 8, k = jj & 255; float s = 0.f;
            for (int c = 0; c < 256; c++) s += W2[k * 1024 + h * 256 + c] * as2[h * 256 + c];
            d_wsrc2[jj] = s;
        } else if (j < 2904) {
            int jj = j - 1880, h = jj >> 8, k = jj & 255; float s = 0.f;
            for (int c = 0; c < 256; c++) s += W2[k * 1024 + h * 256 + c] * ad2[h * 256 + c];
            d_wdst2[jj] = s;
        } else if (j < 3160) {
            int jj = j - 2904, h = jj >> 6, k = jj & 63; float s = 0.f;
            for (int c = 0; c < 256; c++) s += We2[k * 1024 + h * 256 + c] * ag2[h * 256 + c];
            d_wae2[jj] = s;
        } else if (j < 3248) {
            int jj = j - 3160, tt = jj >> 2, h = jj & 3; float s = 0.f;
            for (int c = 0; c < 256; c++) s += etb2[tt * 1024 + h * 256 + c] * ag2[h * 256 + c];
            d_etd2[jj] = s;
        }
    }
}

// ---------------- K2: scan (+ zero d_deg for replay) ----------------
__global__ void k_scan() {
    __shared__ int wsum[32];
    int t = threadIdx.x, base = t * 10, loc[10], sum = 0;
#pragma unroll
    for (int ii = 0; ii < 10; ii++) {
        int i = base + ii;
        int d = (i < Nn) ? d_deg[i] : 0;
        loc[ii] = d; sum += d;
    }
    int lane = t & 31, w = t >> 5;
    int v = sum;
#pragma unroll
    for (int o = 1; o < 32; o <<= 1) {
        int u = __shfl_up_sync(0xffffffffu, v, o);
        if (lane >= o) v += u;
    }
    if (lane == 31) wsum[w] = v;
    __syncthreads();
    if (w == 0) {
        int s = wsum[lane];
#pragma unroll
        for (int o = 1; o < 32; o <<= 1) {
            int u = __shfl_up_sync(0xffffffffu, s, o);
            if (lane >= o) s += u;
        }
        wsum[lane] = s;
    }
    __syncthreads();
    int run = v - sum + (w ? wsum[w - 1] : 0);
#pragma unroll
    for (int ii = 0; ii < 10; ii++) {
        int i = base + ii;
        if (i < Nn) { d_off[i] = run; d_cur[i] = run; d_deg[i] = 0; run += loc[ii]; }
        else if (i == Nn) d_off[Nn] = run;
    }
}

// ---------------- nscore body ----------------
__device__ __forceinline__ void nscore_one(int gw, int lane, const float* xin,
                                           const float* ntemb, int K,
                                           const float* ws, const float* wd, float* u) {
    int nt = d_nt[gw];
    float ps[4] = {0, 0, 0, 0}, pd[4] = {0, 0, 0, 0};
    for (int k = lane; k < K; k += 32) {
        float v = xin[gw * K + k] + ntemb[nt * K + k];
        u[gw * K + k] = v;
#pragma unroll
        for (int h = 0; h < 4; h++) { ps[h] += v * ws[h * K + k]; pd[h] += v * wd[h * K + k]; }
    }
#pragma unroll
    for (int h = 0; h < 4; h++)
        for (int o = 16; o > 0; o >>= 1) {
            ps[h] += __shfl_xor_sync(0xffffffffu, ps[h], o);
            pd[h] += __shfl_xor_sync(0xffffffffu, pd[h], o);
        }
    if (lane == 0)
#pragma unroll
        for (int h = 0; h < 4; h++) { d_ssrc[gw * 4 + h] = ps[h]; d_sdst[gw * 4 + h] = pd[h]; }
}

// ---------------- K3: fused scatter + nscore1 + edgescore ----------------
#define MID_SCAT 1250
#define MID_NS   (MID_SCAT + 1250)
#define MID_TOT  (MID_NS + 40000)

__global__ void k_mid(const float* __restrict__ ea, const float* __restrict__ x,
                      const float* __restrict__ nte1) {
    int b = blockIdx.x, t = threadIdx.x;
    if (b < MID_SCAT) {
        int e = b * 256 + t;
        if (e < Ee) {
            int p = atomicAdd(&d_cur[d_dst[e]], 1);
            d_eid[p] = e; d_srcS[p] = d_src[e]; d_etS[p] = d_et[e];
        }
    } else if (b < MID_NS) {
        int gw = (b - MID_SCAT) * 8 + (t >> 5);
        if (gw < Nn) nscore_one(gw, t & 31, x, nte1, 64, d_wsrc1, d_wdst1, d_u1);
    } else {
        int e = (b - MID_NS) * 8 + (t >> 5);
        int lane = t & 31;
        float a0 = ea[(size_t)e * 64 + lane];
        float a1 = ea[(size_t)e * 64 + 32 + lane];
        float dd1[4], dd2[4];
#pragma unroll
        for (int h = 0; h < 4; h++) {
            dd1[h] = a0 * d_wae1[h * 64 + lane] + a1 * d_wae1[h * 64 + 32 + lane];
            dd2[h] = a0 * d_wae2[h * 64 + lane] + a1 * d_wae2[h * 64 + 32 + lane];
            for (int o = 16; o > 0; o >>= 1) {
                dd1[h] += __shfl_xor_sync(0xffffffffu, dd1[h], o);
                dd2[h] += __shfl_xor_sync(0xffffffffu, dd2[h], o);
            }
        }
        if (lane == 0) {
            int et = d_et[e];
#pragma unroll
            for (int h = 0; h < 4; h++) {
                d_se1[e * 4 + h] = dd1[h] + d_etd1[et * 4 + h];
                d_se2[e * 4 + h] = dd2[h] + d_etd2[et * 4 + h];
            }
        }
    }
}

// ---- warp softmax stats ----
__device__ __forceinline__ void warp_softmax(const float4* se4, int beg, int end,
                                             int lane, float4 sd, float4& m, float4& rdn) {
    const float4* ssrc4 = (const float4*)d_ssrc;
    float4 mx = make_float4(-1e30f, -1e30f, -1e30f, -1e30f);
    for (int i = beg + lane; i < end; i += 32) {
        float4 l = logit4(ssrc4[d_srcS[i]], sd, se4[d_eid[i]]);
        mx.x = fmaxf(mx.x, l.x); mx.y = fmaxf(mx.y, l.y);
        mx.z = fmaxf(mx.z, l.z); mx.w = fmaxf(mx.w, l.w);
    }
    m = warpMax4(mx);
    float4 sm = make_float4(0, 0, 0, 0);
    for (int i = beg + lane; i < end; i += 32) {
        float4 l = logit4(ssrc4[d_srcS[i]], sd, se4[d_eid[i]]);
        sm.x += __expf(l.x - m.x); sm.y += __expf(l.y - m.y);
        sm.z += __expf(l.z - m.z); sm.w += __expf(l.w - m.w);
    }
    float4 den = warpSum4(sm);
    rdn.x = 1.f / (den.x + 1e-16f); rdn.y = 1.f / (den.y + 1e-16f);
    rdn.z = 1.f / (den.z + 1e-16f); rdn.w = 1.f / (den.w + 1e-16f);
}

// ---------------- K4: warp-per-node layer-1 attention (staged alphas) --------
__global__ void __launch_bounds__(256, 4)
k_attn1(const float* __restrict__ ea, const float* __restrict__ x) {
    int wid = threadIdx.x >> 5, lane = threadIdx.x & 31;
    int n = blockIdx.x * 8 + wid;
    __shared__ ull  aSh[8][32][4];   // pre-duplicated alpha pairs
    __shared__ int2 iSh[8][32];      // (src, eid)
    __shared__ float acctSh[8][88];
    for (int i = lane; i < 88; i += 32) acctSh[wid][i] = 0.f;
    __syncwarp();
    int beg = d_off[n], end = d_off[n + 1], nE = end - beg;
    ull ax[4] = {0, 0, 0, 0}, av[4] = {0, 0, 0, 0};
    if (nE > 0) {
        const float4* ssrc4 = (const float4*)d_ssrc;
        const float4* se4 = (const float4*)d_se1;
        float4 sd = ((const float4*)d_sdst)[n];
        float4 m, rdn;
        warp_softmax(se4, beg, end, lane, sd, m, rdn);
        for (int c0 = beg; c0 < end; c0 += 32) {
            int nc = min(32, end - c0);
            if (lane < nc) {
                int i = c0 + lane;
                int s = d_srcS[i], e = d_eid[i], et = d_etS[i];
                float4 l = logit4(ssrc4[s], sd, se4[e]);
                float a0 = __expf(l.x - m.x) * rdn.x, a1 = __expf(l.y - m.y) * rdn.y;
                float a2 = __expf(l.z - m.z) * rdn.z, a3 = __expf(l.w - m.w) * rdn.w;
                aSh[wid][lane][0] = dup2(a0); aSh[wid][lane][1] = dup2(a1);
                aSh[wid][lane][2] = dup2(a2); aSh[wid][lane][3] = dup2(a3);
                iSh[wid][lane] = make_int2(s, e);
                atomicAdd(&acctSh[wid][et], a0);
                atomicAdd(&acctSh[wid][22 + et], a1);
                atomicAdd(&acctSh[wid][44 + et], a2);
                atomicAdd(&acctSh[wid][66 + et], a3);
            }
            __syncwarp();
#pragma unroll 4
            for (int j = 0; j < nc; j++) {
                ull b0 = aSh[wid][j][0], b1 = aSh[wid][j][1];
                ull b2 = aSh[wid][j][2], b3 = aSh[wid][j][3];
                int2 se = iSh[wid][j];
                ull u = *(const ull*)&d_u1[se.x * 64 + lane * 2];
                ull a = *(const ull*)&ea[(size_t)se.y * 64 + lane * 2];
                fma2(ax[0], u, b0); fma2(ax[1], u, b1);
                fma2(ax[2], u, b2); fma2(ax[3], u, b3);
                fma2(av[0], a, b0); fma2(av[1], a, b1);
                fma2(av[2], a, b2); fma2(av[3], a, b3);
            }
            __syncwarp();
        }
    }
    __syncwarp();
    float* v = &d_v1[(size_t)n * LDA1];
    int c = lane * 2;
#pragma unroll
    for (int h = 0; h < 4; h++) {
        *(ull*)&v[h * K1H + c] = ax[h];
        *(ull*)&v[h * K1H + 64 + c] = av[h];
        *(ull*)&v[h * K1H + 150 + c] = *(const ull*)&x[n * 64 + c];
    }
    for (int i = lane; i < 88; i += 32) {
        int hh = i / 22, t2 = i % 22;
        v[hh * K1H + 128 + t2] = acctSh[wid][hh * 22 + t2];
    }
    if (lane < 8) v[(lane >> 1) * K1H + 214 + (lane & 1)] = 0.f;
}

// ---------------- K6: nscore layer 2 ----------------
__global__ void k_ns2(const float* __restrict__ nte2) {
    int gw = (blockIdx.x * blockDim.x + threadIdx.x) >> 5;
    if (gw < Nn) nscore_one(gw, threadIdx.x & 31, d_h1, nte2, 256, d_wsrc2, d_wdst2, d_u2);
}

// ---------------- K7: 2-warps-per-node layer-2 attention ----------------
__global__ void __launch_bounds__(256, 4)
k_attn2(const float* __restrict__ ea) {
    int wid = threadIdx.x >> 5, lane = threadIdx.x & 31;
    int pair = wid >> 1, half = wid & 1;
    int n = blockIdx.x * 4 + pair;
    __shared__ ull  aSh[8][32][4];
    __shared__ int2 iSh[8][32];
    __shared__ float acctSh[4][88];
    if (half == 0) { for (int i = lane; i < 88; i += 32) acctSh[pair][i] = 0.f; }
    __syncwarp();
    int beg = d_off[n], end = d_off[n + 1], nE = end - beg;
    int fbase = half * 128 + lane * 4;
    ull axu[4][2];
#pragma unroll
    for (int h = 0; h < 4; h++) { axu[h][0] = 0ull; axu[h][1] = 0ull; }
    ull av[4] = {0, 0, 0, 0};
    if (nE > 0) {
        const float4* ssrc4 = (const float4*)d_ssrc;
        const float4* se4 = (const float4*)d_se2;
        float4 sd = ((const float4*)d_sdst)[n];
        float4 m, rdn;
        warp_softmax(se4, beg, end, lane, sd, m, rdn);
        for (int c0 = beg; c0 < end; c0 += 32) {
            int nc = min(32, end - c0);
            if (lane < nc) {
                int i = c0 + lane;
                int s = d_srcS[i], e = d_eid[i], et = d_etS[i];
                float4 l = logit4(ssrc4[s], sd, se4[e]);
                float a0 = __expf(l.x - m.x) * rdn.x, a1 = __expf(l.y - m.y) * rdn.y;
                float a2 = __expf(l.z - m.z) * rdn.z, a3 = __expf(l.w - m.w) * rdn.w;
                aSh[wid][lane][0] = dup2(a0); aSh[wid][lane][1] = dup2(a1);
                aSh[wid][lane][2] = dup2(a2); aSh[wid][lane][3] = dup2(a3);
                iSh[wid][lane] = make_int2(s, e);
                if (half == 0) {
                    atomicAdd(&acctSh[pair][et], a0);
                    atomicAdd(&acctSh[pair][22 + et], a1);
                    atomicAdd(&acctSh[pair][44 + et], a2);
                    atomicAdd(&acctSh[pair][66 + et], a3);
                }
            }
            __syncwarp();
#pragma unroll 2
            for (int j = 0; j < nc; j++) {
                ull b0 = aSh[wid][j][0], b1 = aSh[wid][j][1];
                ull b2 = aSh[wid][j][2], b3 = aSh[wid][j][3];
                int2 se = iSh[wid][j];
                float4 u0 = *(const float4*)&d_u2[se.x * 256 + fbase];
                ull p0 = *(ull*)&u0.x, p1 = *(ull*)&u0.z;
                fma2(axu[0][0], p0, b0); fma2(axu[0][1], p1, b0);
                fma2(axu[1][0], p0, b1); fma2(axu[1][1], p1, b1);
                fma2(axu[2][0], p0, b2); fma2(axu[2][1], p1, b2);
                fma2(axu[3][0], p0, b3); fma2(axu[3][1], p1, b3);
                if (half == 0) {
                    ull a = *(const ull*)&ea[(size_t)se.y * 64 + lane * 2];
                    fma2(av[0], a, b0); fma2(av[1], a, b1);
                    fma2(av[2], a, b2); fma2(av[3], a, b3);
                }
            }
            __syncwarp();
        }
    }
    __syncwarp();
    float* v = &d_v2[(size_t)n * K2P];
#pragma unroll
    for (int h = 0; h < 4; h++) {
        *(ull*)&v[h * 256 + fbase] = axu[h][0];
        *(ull*)&v[h * 256 + fbase + 2] = axu[h][1];
    }
    if (half == 0) {
#pragma unroll
        for (int h = 0; h < 4; h++) *(ull*)&v[1024 + h * 64 + lane * 2] = av[h];
        for (int i = lane; i < 88; i += 32) v[1280 + i] = acctSh[pair][i];
        if (lane < 8) v[1368 + lane] = 0.f;
    }
}

// ---------------- f32x2 packed SGEMM ----------------
template <int K, int MODE>
__global__ void k_gemmT(const float* __restrict__ A, const float* __restrict__ B,
                        const float* __restrict__ bias, const float* __restrict__ add,
                        float* __restrict__ C) {
    constexpr int LDA = (MODE == 1) ? LDA1 : K2P;
    __shared__ float As[8][132];
    __shared__ float Bs[8][64];
    int y = blockIdx.y;
    int bm = blockIdx.x * 128;
    int colbase = y * 64;
    const float* Ab = A + ((MODE == 1) ? y * K1H : 0);
    const float* Bb = (MODE == 1) ? (B + y * K1H * 64) : (B + colbase);
    const int ldb = (MODE == 1) ? 64 : 256;
    int tid = threadIdx.x;
    int tx = tid & 15, ty = tid >> 4;
    int lrow = tid >> 1, lk = (tid & 1) * 4;
    int brow = tid >> 4, bcol = (tid & 15) * 4;
    ull acc[4][4];
#pragma unroll
    for (int p = 0; p < 4; p++)
#pragma unroll
        for (int j = 0; j < 4; j++) acc[p][j] = 0ull;
    for (int k0 = 0; k0 < K; k0 += 8) {
        float4 avv = make_float4(0, 0, 0, 0);
        int row = bm + lrow;
        if (row < Nn) avv = *(const float4*)&Ab[(size_t)row * LDA + k0 + lk];
        As[lk + 0][lrow] = avv.x; As[lk + 1][lrow] = avv.y;
        As[lk + 2][lrow] = avv.z; As[lk + 3][lrow] = avv.w;
        if (tid < 128) {
            float4 bv = *(const float4*)&Bb[(size_t)(k0 + brow) * ldb + bcol];
            *(float4*)&Bs[brow][bcol] = bv;
        }
        __syncthreads();
#pragma unroll
        for (int kk = 0; kk < 8; kk++) {
            ulonglong2 a01 = *(const ulonglong2*)&As[kk][ty * 8];
            ulonglong2 a23 = *(const ulonglong2*)&As[kk][ty * 8 + 4];
            float4 bv = *(const float4*)&Bs[kk][tx * 4];
            ull ap[4] = {a01.x, a01.y, a23.x, a23.y};
            ull bd[4] = {dup2(bv.x), dup2(bv.y), dup2(bv.z), dup2(bv.w)};
#pragma unroll
            for (int p = 0; p < 4; p++)
#pragma unroll
                for (int j = 0; j < 4; j++) fma2(acc[p][j], ap[p], bd[j]);
        }
        __syncthreads();
    }
#pragma unroll
    for (int p = 0; p < 4; p++) {
        int r0 = bm + ty * 8 + 2 * p;
#pragma unroll
        for (int j = 0; j < 4; j++) {
            int col = colbase + tx * 4 + j;
            float lo = __uint_as_float((unsigned)(acc[p][j] & 0xffffffffull));
            float hi = __uint_as_float((unsigned)(acc[p][j] >> 32));
            float bsv = bias[col];
            if (r0 < Nn) {
                float v = lo + bsv;
                if (MODE == 1) v = fmaxf(v, 0.f);
                else v += add[r0 * 256 + col];
                C[r0 * 256 + col] = v;
            }
            if (r0 + 1 < Nn) {
                float v = hi + bsv;
                if (MODE == 1) v = fmaxf(v, 0.f);
                else v += add[(r0 + 1) * 256 + col];
                C[(r0 + 1) * 256 + col] = v;
            }
        }
    }
}

// ---------------- launch ----------------
extern "C" void kernel_launch(void* const* d_in, const int* in_sizes, int n_in,
                              void* d_out, int out_size) {
    const float* x    = (const float*)d_in[0];
    const void*  ei   = d_in[1];
    const void*  ntp  = d_in[2];
    const float* ea   = (const float*)d_in[3];
    const void*  etp  = d_in[4];
    const float* W1   = (const float*)d_in[5];
    const float* b1   = (const float*)d_in[6];
    const float* We1  = (const float*)d_in[7];
    const float* nte1 = (const float*)d_in[8];
    const float* ete1 = (const float*)d_in[9];
    const float* as1  = (const float*)d_in[10];
    const float* ad1  = (const float*)d_in[11];
    const float* ag1  = (const float*)d_in[12];
    const float* res1 = (const float*)d_in[13];
    const float* W2   = (const float*)d_in[14];
    const float* b2   = (const float*)d_in[15];
    const float* We2  = (const float*)d_in[16];
    const float* nte2 = (const float*)d_in[17];
    const float* ete2 = (const float*)d_in[18];
    const float* as2  = (const float*)d_in[19];
    const float* ad2  = (const float*)d_in[20];
    const float* ag2  = (const float*)d_in[21];
    float* out = (float*)d_out;

    k_pre<<<PRE_TOT, 256>>>(ei, ntp, etp, W1, as1, ad1, We1, ag1, ete1,
                            W2, as2, ad2, We2, ag2, ete2, res1);
    k_scan<<<1, 1024>>>();
    k_mid<<<MID_TOT, 256>>>(ea, x, nte1);
    k_attn1<<<Nn / 8, 256>>>(ea, x);

    float* h1;  cudaGetSymbolAddress((void**)&h1, d_h1);
    float* v1;  cudaGetSymbolAddress((void**)&v1, d_v1);
    float* w1h; cudaGetSymbolAddress((void**)&w1h, d_W1h);
    float* v2;  cudaGetSymbolAddress((void**)&v2, d_v2);
    float* w2c; cudaGetSymbolAddress((void**)&w2c, d_W2cat);
    dim3 g((Nn + 127) / 128, 4);
    k_gemmT<K1H, 1><<<g, 256>>>(v1, w1h, b1, nullptr, h1);
    k_ns2<<<(Nn * 32 + 255) / 256, 256>>>(nte2);
    k_attn2<<<Nn / 4, 256>>>(ea);
    k_gemmT<K2P, 2><<<g, 256>>>(v2, w2c, b2, h1, out);
}